// round 2
// baseline (speedup 1.0000x reference)
#include <cuda_runtime.h>
#include <cmath>

// ------------------------------------------------------------------
// Problem constants
// ------------------------------------------------------------------
#define B_     16
#define N_     577
#define C_     768
#define HEADS_ 12
#define HD_    64
#define HID_   3072
#define M_     (B_ * N_)        // 9232 rows

// ------------------------------------------------------------------
// Static scratch (allocation-free rule: __device__ globals)
// ------------------------------------------------------------------
__device__ float g_h   [M_ * C_];      // LN output (reused for LN1 and LN2)
__device__ float g_qkv [M_ * 3 * C_];  // QKV
__device__ float g_att [M_ * C_];      // attention output (B,N,C)
__device__ float g_x1  [M_ * C_];      // after attention residual
__device__ float g_fc1 [M_ * HID_];    // GELU(fc1)

// ------------------------------------------------------------------
// LayerNorm: one block per row of 768
// ------------------------------------------------------------------
__global__ void ln_kernel(const float* __restrict__ x,
                          const float* __restrict__ g,
                          const float* __restrict__ b,
                          float* __restrict__ out) {
    int row = blockIdx.x;
    const float* xr = x + (size_t)row * C_;
    float sum = 0.f, sumsq = 0.f;
    for (int i = threadIdx.x; i < C_; i += blockDim.x) {
        float v = xr[i];
        sum += v; sumsq += v * v;
    }
    __shared__ float s1[8], s2[8];
    for (int o = 16; o; o >>= 1) {
        sum   += __shfl_down_sync(0xffffffffu, sum, o);
        sumsq += __shfl_down_sync(0xffffffffu, sumsq, o);
    }
    int wid = threadIdx.x >> 5, lid = threadIdx.x & 31;
    if (lid == 0) { s1[wid] = sum; s2[wid] = sumsq; }
    __syncthreads();
    if (wid == 0) {
        sum   = (lid < 8) ? s1[lid] : 0.f;
        sumsq = (lid < 8) ? s2[lid] : 0.f;
        for (int o = 4; o; o >>= 1) {
            sum   += __shfl_down_sync(0xffffffffu, sum, o);
            sumsq += __shfl_down_sync(0xffffffffu, sumsq, o);
        }
        if (lid == 0) { s1[0] = sum; s2[0] = sumsq; }
    }
    __syncthreads();
    float mu   = s1[0] * (1.f / C_);
    float var  = s2[0] * (1.f / C_) - mu * mu;
    float rstd = rsqrtf(var + 1e-5f);
    float* orow = out + (size_t)row * C_;
    for (int i = threadIdx.x; i < C_; i += blockDim.x)
        orow[i] = (xr[i] - mu) * rstd * g[i] + b[i];
}

// ------------------------------------------------------------------
// Tiled SGEMM: C = epi(A[MxK] @ B[KxN] + bias [, + res])
// Tile 128x128, BK=16, 256 threads, 8x8 microtile.
// N and K are multiples of 16/128; only M needs guards.
// ------------------------------------------------------------------
#define EPI_BIAS      0
#define EPI_BIAS_RES  1
#define EPI_BIAS_GELU 2

template <int EPI>
__global__ __launch_bounds__(256)
void gemm_kernel(const float* __restrict__ A, const float* __restrict__ Bm,
                 const float* __restrict__ bias, const float* __restrict__ res,
                 float* __restrict__ C, int M, int N, int K) {
    __shared__ float As[16][128];   // transposed: As[k][m]
    __shared__ float Bs[16][128];   // Bs[k][n]

    const int bn = blockIdx.x, bm = blockIdx.y;
    const int tid = threadIdx.x;
    const int tx = tid & 15, ty = tid >> 4;
    const int row0 = bm * 128, col0 = bn * 128;

    float acc[8][8];
#pragma unroll
    for (int i = 0; i < 8; i++)
#pragma unroll
        for (int j = 0; j < 8; j++) acc[i][j] = 0.f;

    for (int k0 = 0; k0 < K; k0 += 16) {
        // --- load A tile 128x16 (guarded on M) ---
        {
            int r  = tid >> 2;          // 0..63
            int c4 = (tid & 3) * 4;     // 0,4,8,12
#pragma unroll
            for (int p = 0; p < 2; p++) {
                int rr  = r + p * 64;
                int row = row0 + rr;
                float4 v = make_float4(0.f, 0.f, 0.f, 0.f);
                if (row < M)
                    v = *reinterpret_cast<const float4*>(&A[(size_t)row * K + k0 + c4]);
                As[c4 + 0][rr] = v.x; As[c4 + 1][rr] = v.y;
                As[c4 + 2][rr] = v.z; As[c4 + 3][rr] = v.w;
            }
        }
        // --- load B tile 16x128 (no guards needed) ---
        {
            int r  = tid >> 4;          // 0..15
            int c4 = (tid & 15) * 4;    // 0..60
#pragma unroll
            for (int p = 0; p < 2; p++) {
                float4 v = *reinterpret_cast<const float4*>(
                    &Bm[(size_t)(k0 + r) * N + col0 + c4 + p * 64]);
                *reinterpret_cast<float4*>(&Bs[r][c4 + p * 64]) = v;
            }
        }
        __syncthreads();

#pragma unroll
        for (int kk = 0; kk < 16; kk++) {
            float4 a0 = *reinterpret_cast<const float4*>(&As[kk][ty * 8]);
            float4 a1 = *reinterpret_cast<const float4*>(&As[kk][ty * 8 + 4]);
            float4 b0 = *reinterpret_cast<const float4*>(&Bs[kk][tx * 8]);
            float4 b1 = *reinterpret_cast<const float4*>(&Bs[kk][tx * 8 + 4]);
            float a[8] = {a0.x, a0.y, a0.z, a0.w, a1.x, a1.y, a1.z, a1.w};
            float b[8] = {b0.x, b0.y, b0.z, b0.w, b1.x, b1.y, b1.z, b1.w};
#pragma unroll
            for (int i = 0; i < 8; i++)
#pragma unroll
                for (int j = 0; j < 8; j++) acc[i][j] += a[i] * b[j];
        }
        __syncthreads();
    }

    // --- epilogue ---
#pragma unroll
    for (int i = 0; i < 8; i++) {
        int row = row0 + ty * 8 + i;
        if (row >= M) continue;
#pragma unroll
        for (int j = 0; j < 8; j++) {
            int col = col0 + tx * 8 + j;
            float v = acc[i][j] + bias[col];
            if (EPI == EPI_BIAS_RES)  v += res[(size_t)row * N + col];
            if (EPI == EPI_BIAS_GELU) v = 0.5f * v * (1.f + erff(v * 0.70710678118654752f));
            C[(size_t)row * N + col] = v;
        }
    }
}

// ------------------------------------------------------------------
// Flash-style attention: grid (ceil(N/32), HEADS, B), 256 threads.
// Each block: 32 query rows x full key loop (tiles of 64), online softmax.
// Thread t owns row r = t>>3, d-columns cg*8..cg*8+7 (cg = t&7).
// ------------------------------------------------------------------
__global__ __launch_bounds__(256)
void attn_kernel(const float* __restrict__ qkv, float* __restrict__ out) {
    __shared__ float Qs[32][64];
    __shared__ float Kt[64][64];   // transposed: Kt[d][key]
    __shared__ float Vs[64][64];   // Vs[key][d]
    __shared__ float S [32][64];

    const int qt = blockIdx.x, h = blockIdx.y, b = blockIdx.z;
    const int tid = threadIdx.x;
    const int r  = tid >> 3;
    const int cg = tid & 7;

    // load Q tile
    for (int i = tid; i < 32 * 64; i += 256) {
        int rr = i >> 6, d = i & 63;
        int n = qt * 32 + rr;
        Qs[rr][d] = (n < N_) ? qkv[((size_t)(b * N_ + n)) * (3 * C_) + h * HD_ + d] : 0.f;
    }

    float acc[8] = {0.f, 0.f, 0.f, 0.f, 0.f, 0.f, 0.f, 0.f};
    float m = -1e30f, l = 0.f;

    for (int j0 = 0; j0 < N_; j0 += 64) {
        // load K (transposed) and V tiles
        for (int i = tid; i < 64 * 64; i += 256) {
            int kk = i >> 6, d = i & 63;
            int n = j0 + kk;
            float kv = 0.f, vv = 0.f;
            if (n < N_) {
                size_t base = ((size_t)(b * N_ + n)) * (3 * C_) + h * HD_ + d;
                kv = qkv[base + C_];
                vv = qkv[base + 2 * C_];
            }
            Kt[d][kk] = kv;
            Vs[kk][d] = vv;
        }
        __syncthreads();

        // scores for (row r, cols cg*8..+7)
        float s[8] = {0.f, 0.f, 0.f, 0.f, 0.f, 0.f, 0.f, 0.f};
#pragma unroll 8
        for (int d = 0; d < 64; d++) {
            float qv = Qs[r][d];
            float4 k0 = *reinterpret_cast<const float4*>(&Kt[d][cg * 8]);
            float4 k1 = *reinterpret_cast<const float4*>(&Kt[d][cg * 8 + 4]);
            s[0] += qv * k0.x; s[1] += qv * k0.y; s[2] += qv * k0.z; s[3] += qv * k0.w;
            s[4] += qv * k1.x; s[5] += qv * k1.y; s[6] += qv * k1.z; s[7] += qv * k1.w;
        }
#pragma unroll
        for (int jj = 0; jj < 8; jj++) {
            int col = cg * 8 + jj;
            S[r][col] = (j0 + col < N_) ? s[jj] * 0.125f : -1e30f;
        }
        __syncthreads();

        // row max (redundant across the 8 threads of a row)
        float mt = -1e30f;
#pragma unroll 8
        for (int c = 0; c < 64; c++) mt = fmaxf(mt, S[r][c]);
        float mn  = fmaxf(m, mt);
        float fac = __expf(m - mn);
        __syncthreads();            // all raw-score reads done

        // overwrite own entries with p = exp(s - mn)
#pragma unroll
        for (int jj = 0; jj < 8; jj++) {
            int col = cg * 8 + jj;
            S[r][col] = __expf(S[r][col] - mn);
        }
        __syncthreads();

        // accumulate
        float lsum = 0.f;
#pragma unroll
        for (int i = 0; i < 8; i++) acc[i] *= fac;
        for (int c = 0; c < 64; c++) {
            float p = S[r][c];
            lsum += p;
            float4 v0 = *reinterpret_cast<const float4*>(&Vs[c][cg * 8]);
            float4 v1 = *reinterpret_cast<const float4*>(&Vs[c][cg * 8 + 4]);
            acc[0] += p * v0.x; acc[1] += p * v0.y; acc[2] += p * v0.z; acc[3] += p * v0.w;
            acc[4] += p * v1.x; acc[5] += p * v1.y; acc[6] += p * v1.z; acc[7] += p * v1.w;
        }
        l = l * fac + lsum;
        m = mn;
        __syncthreads();            // before next tile overwrites K/V/S
    }

    int n = qt * 32 + r;
    if (n < N_) {
        float inv = 1.f / l;
        float* o = out + ((size_t)(b * N_ + n)) * C_ + h * HD_ + cg * 8;
#pragma unroll
        for (int i = 0; i < 8; i++) o[i] = acc[i] * inv;
    }
}

// ------------------------------------------------------------------
// Launch
// ------------------------------------------------------------------
extern "C" void kernel_launch(void* const* d_in, const int* in_sizes, int n_in,
                              void* d_out, int out_size) {
    const float* x      = (const float*)d_in[0];
    const float* ln1_g  = (const float*)d_in[1];
    const float* ln1_b  = (const float*)d_in[2];
    const float* w_qkv  = (const float*)d_in[3];
    const float* b_qkv  = (const float*)d_in[4];
    const float* w_proj = (const float*)d_in[5];
    const float* b_proj = (const float*)d_in[6];
    const float* ln2_g  = (const float*)d_in[7];
    const float* ln2_b  = (const float*)d_in[8];
    const float* w_fc1  = (const float*)d_in[9];
    const float* b_fc1  = (const float*)d_in[10];
    const float* w_fc2  = (const float*)d_in[11];
    const float* b_fc2  = (const float*)d_in[12];
    float* out = (float*)d_out;

    float *h, *qkv, *att, *x1, *fc1;
    cudaGetSymbolAddress((void**)&h,   g_h);
    cudaGetSymbolAddress((void**)&qkv, g_qkv);
    cudaGetSymbolAddress((void**)&att, g_att);
    cudaGetSymbolAddress((void**)&x1,  g_x1);
    cudaGetSymbolAddress((void**)&fc1, g_fc1);

    const int MB = (M_ + 127) / 128;   // 73

    // 1) LN1
    ln_kernel<<<M_, 256>>>(x, ln1_g, ln1_b, h);
    // 2) QKV = h @ w_qkv + b_qkv     [9232 x 2304]
    gemm_kernel<EPI_BIAS><<<dim3(3 * C_ / 128, MB), 256>>>(h, w_qkv, b_qkv, nullptr, qkv, M_, 3 * C_, C_);
    // 3) attention
    attn_kernel<<<dim3((N_ + 31) / 32, HEADS_, B_), 256>>>(qkv, att);
    // 4) x1 = x + att @ w_proj + b_proj
    gemm_kernel<EPI_BIAS_RES><<<dim3(C_ / 128, MB), 256>>>(att, w_proj, b_proj, x, x1, M_, C_, C_);
    // 5) LN2
    ln_kernel<<<M_, 256>>>(x1, ln2_g, ln2_b, h);
    // 6) fc1 = gelu(h @ w_fc1 + b_fc1)   [9232 x 3072]
    gemm_kernel<EPI_BIAS_GELU><<<dim3(HID_ / 128, MB), 256>>>(h, w_fc1, b_fc1, nullptr, fc1, M_, HID_, C_);
    // 7) out = x1 + fc1 @ w_fc2 + b_fc2
    gemm_kernel<EPI_BIAS_RES><<<dim3(C_ / 128, MB), 256>>>(fc1, w_fc2, b_fc2, x1, out, M_, C_, HID_);
}

// round 3
// speedup vs baseline: 1.5822x; 1.5822x over previous
#include <cuda_runtime.h>
#include <cmath>
#include <cstdint>

// ------------------------------------------------------------------
// Problem constants
// ------------------------------------------------------------------
#define B_     16
#define N_     577
#define C_     768
#define HEADS_ 12
#define HD_    64
#define HID_   3072
#define M_     (B_ * N_)        // 9232 rows

// ------------------------------------------------------------------
// Static scratch
// ------------------------------------------------------------------
__device__ float g_h   [M_ * C_];
__device__ float g_qkv [M_ * 3 * C_];
__device__ float g_att [M_ * C_];
__device__ float g_x1  [M_ * C_];
__device__ float g_fc1 [M_ * HID_];

// ------------------------------------------------------------------
// LayerNorm
// ------------------------------------------------------------------
__global__ void ln_kernel(const float* __restrict__ x,
                          const float* __restrict__ g,
                          const float* __restrict__ b,
                          float* __restrict__ out) {
    int row = blockIdx.x;
    const float* xr = x + (size_t)row * C_;
    float sum = 0.f, sumsq = 0.f;
    for (int i = threadIdx.x; i < C_; i += blockDim.x) {
        float v = xr[i];
        sum += v; sumsq += v * v;
    }
    __shared__ float s1[8], s2[8];
    for (int o = 16; o; o >>= 1) {
        sum   += __shfl_down_sync(0xffffffffu, sum, o);
        sumsq += __shfl_down_sync(0xffffffffu, sumsq, o);
    }
    int wid = threadIdx.x >> 5, lid = threadIdx.x & 31;
    if (lid == 0) { s1[wid] = sum; s2[wid] = sumsq; }
    __syncthreads();
    if (wid == 0) {
        sum   = (lid < 8) ? s1[lid] : 0.f;
        sumsq = (lid < 8) ? s2[lid] : 0.f;
        for (int o = 4; o; o >>= 1) {
            sum   += __shfl_down_sync(0xffffffffu, sum, o);
            sumsq += __shfl_down_sync(0xffffffffu, sumsq, o);
        }
        if (lid == 0) { s1[0] = sum; s2[0] = sumsq; }
    }
    __syncthreads();
    float mu   = s1[0] * (1.f / C_);
    float var  = s2[0] * (1.f / C_) - mu * mu;
    float rstd = rsqrtf(var + 1e-5f);
    float* orow = out + (size_t)row * C_;
    for (int i = threadIdx.x; i < C_; i += blockDim.x)
        orow[i] = (xr[i] - mu) * rstd * g[i] + b[i];
}

// ------------------------------------------------------------------
// tf32 tensor-core helpers
// ------------------------------------------------------------------
__device__ __forceinline__ uint32_t cvt_tf32(float x) {
    uint32_t r;
    asm("cvt.rna.tf32.f32 %0, %1;" : "=r"(r) : "f"(x));
    return r;
}

__device__ __forceinline__ void mma_tf32(float& d0, float& d1, float& d2, float& d3,
                                         uint32_t a0, uint32_t a1, uint32_t a2, uint32_t a3,
                                         uint32_t b0, uint32_t b1) {
    asm volatile(
        "mma.sync.aligned.m16n8k8.row.col.f32.tf32.tf32.f32 "
        "{%0,%1,%2,%3}, {%4,%5,%6,%7}, {%8,%9}, {%0,%1,%2,%3};"
        : "+f"(d0), "+f"(d1), "+f"(d2), "+f"(d3)
        : "r"(a0), "r"(a1), "r"(a2), "r"(a3), "r"(b0), "r"(b1));
}

__device__ __forceinline__ void cp_async16(uint32_t dst_smem, const void* src, bool pred) {
    int sz = pred ? 16 : 0;
    asm volatile("cp.async.cg.shared.global [%0], [%1], 16, %2;"
                 :: "r"(dst_smem), "l"(src), "r"(sz));
}

// ------------------------------------------------------------------
// tf32 tensor-core GEMM: C = epi(A[MxK] @ B[KxN] + bias [, + res])
// 128x128x32 tiles, 8 warps (2x4), warp tile 64x32 (4x4 m16n8k8 frags).
// XOR-swizzled smem -> conflict-free fragment loads:
//   As[m][k']  k' = k ^ (4*(m&7)),  stride 32 floats
//   Bs[k][n']  n' = n ^ (8*(k&3)),  stride 128 floats
// cp.async double buffer, 64KB dynamic smem.
// ------------------------------------------------------------------
#define EPI_BIAS      0
#define EPI_BIAS_RES  1
#define EPI_BIAS_GELU 2

#define A_TILE (128 * 32)
#define B_TILE (32 * 128)

template <int EPI>
__global__ __launch_bounds__(256)
void gemm_tc(const float* __restrict__ A, const float* __restrict__ Bm,
             const float* __restrict__ bias, const float* __restrict__ res,
             float* __restrict__ C, int M, int N, int K) {
    extern __shared__ float smem[];
    float* As = smem;               // [2][128][32]
    float* Bs = smem + 2 * A_TILE;  // [2][32][128]

    const int tid  = threadIdx.x;
    const int wid  = tid >> 5, lane = tid & 31;
    const int wm   = wid >> 2, wn = wid & 3;     // 2 x 4 warp grid
    const int row0 = blockIdx.y * 128, col0 = blockIdx.x * 128;

    // cp.async mappings
    const int m_a  = tid >> 3;           // A: row within tile (0..31, +32*p)
    const int kg_a = (tid & 7) * 4;      // A: k group
    const int k_b  = tid >> 5;           // B: k row (0..7, +8*p)
    const int ng_b = (tid & 31) * 4;     // B: n group

    float acc[4][4][4];
#pragma unroll
    for (int i = 0; i < 4; i++)
#pragma unroll
        for (int j = 0; j < 4; j++)
#pragma unroll
            for (int t = 0; t < 4; t++) acc[i][j][t] = 0.f;

    const int nIter = K / 32;

    auto load_tiles = [&](int k0, int buf) {
        float* Ab = As + buf * A_TILE;
        float* Bb = Bs + buf * B_TILE;
#pragma unroll
        for (int p = 0; p < 4; p++) {
            int m   = m_a + p * 32;
            int row = row0 + m;
            uint32_t dst = (uint32_t)__cvta_generic_to_shared(
                Ab + m * 32 + (kg_a ^ (4 * (m & 7))));
            cp_async16(dst, A + (size_t)row * K + k0 + kg_a, row < M);
        }
#pragma unroll
        for (int p = 0; p < 4; p++) {
            int k = k_b + p * 8;
            uint32_t dst = (uint32_t)__cvta_generic_to_shared(
                Bb + k * 128 + (ng_b ^ (8 * (k & 3))));
            cp_async16(dst, Bm + (size_t)(k0 + k) * N + col0 + ng_b, true);
        }
        asm volatile("cp.async.commit_group;");
    };

    load_tiles(0, 0);

    const int fr = lane >> 2;
    const int fc = lane & 3;

    for (int it = 0; it < nIter; ++it) {
        if (it + 1 < nIter) {
            load_tiles((it + 1) * 32, (it + 1) & 1);
            asm volatile("cp.async.wait_group 1;");
        } else {
            asm volatile("cp.async.wait_group 0;");
        }
        __syncthreads();

        const float* Ab = As + (it & 1) * A_TILE;
        const float* Bb = Bs + (it & 1) * B_TILE;
        const int xa = 4 * fr;

#pragma unroll
        for (int ks = 0; ks < 4; ks++) {
            const int k0 = ks * 8 + fc;
            const int xb = 8 * fc;
            uint32_t af[4][4], bf[4][2];
#pragma unroll
            for (int mt = 0; mt < 4; mt++) {
                int m0 = wm * 64 + mt * 16 + fr;
                af[mt][0] = cvt_tf32(Ab[(m0)     * 32 + ((k0)     ^ xa)]);
                af[mt][1] = cvt_tf32(Ab[(m0 + 8) * 32 + ((k0)     ^ xa)]);
                af[mt][2] = cvt_tf32(Ab[(m0)     * 32 + ((k0 + 4) ^ xa)]);
                af[mt][3] = cvt_tf32(Ab[(m0 + 8) * 32 + ((k0 + 4) ^ xa)]);
            }
#pragma unroll
            for (int nt = 0; nt < 4; nt++) {
                int n0 = wn * 32 + nt * 8 + fr;
                bf[nt][0] = cvt_tf32(Bb[(k0)     * 128 + (n0 ^ xb)]);
                bf[nt][1] = cvt_tf32(Bb[(k0 + 4) * 128 + (n0 ^ xb)]);
            }
#pragma unroll
            for (int mt = 0; mt < 4; mt++)
#pragma unroll
                for (int nt = 0; nt < 4; nt++)
                    mma_tf32(acc[mt][nt][0], acc[mt][nt][1], acc[mt][nt][2], acc[mt][nt][3],
                             af[mt][0], af[mt][1], af[mt][2], af[mt][3],
                             bf[nt][0], bf[nt][1]);
        }
        __syncthreads();
    }

    // ---- epilogue ----
    const int c2 = fc * 2;
#pragma unroll
    for (int mt = 0; mt < 4; mt++) {
#pragma unroll
        for (int half = 0; half < 2; half++) {
            int row = row0 + wm * 64 + mt * 16 + fr + half * 8;
            if (row >= M) continue;
#pragma unroll
            for (int nt = 0; nt < 4; nt++) {
                int col = col0 + wn * 32 + nt * 8 + c2;
                float v0 = acc[mt][nt][half * 2 + 0] + bias[col];
                float v1 = acc[mt][nt][half * 2 + 1] + bias[col + 1];
                if (EPI == EPI_BIAS_RES) {
                    v0 += res[(size_t)row * N + col];
                    v1 += res[(size_t)row * N + col + 1];
                }
                if (EPI == EPI_BIAS_GELU) {
                    v0 = 0.5f * v0 * (1.f + erff(v0 * 0.70710678118654752f));
                    v1 = 0.5f * v1 * (1.f + erff(v1 * 0.70710678118654752f));
                }
                *reinterpret_cast<float2*>(&C[(size_t)row * N + col]) = make_float2(v0, v1);
            }
        }
    }
}

// ------------------------------------------------------------------
// Flash-style attention (unchanged this round)
// ------------------------------------------------------------------
__global__ __launch_bounds__(256)
void attn_kernel(const float* __restrict__ qkv, float* __restrict__ out) {
    __shared__ float Qs[32][64];
    __shared__ float Kt[64][64];
    __shared__ float Vs[64][64];
    __shared__ float S [32][64];

    const int qt = blockIdx.x, h = blockIdx.y, b = blockIdx.z;
    const int tid = threadIdx.x;
    const int r  = tid >> 3;
    const int cg = tid & 7;

    for (int i = tid; i < 32 * 64; i += 256) {
        int rr = i >> 6, d = i & 63;
        int n = qt * 32 + rr;
        Qs[rr][d] = (n < N_) ? qkv[((size_t)(b * N_ + n)) * (3 * C_) + h * HD_ + d] : 0.f;
    }

    float acc[8] = {0.f, 0.f, 0.f, 0.f, 0.f, 0.f, 0.f, 0.f};
    float m = -1e30f, l = 0.f;

    for (int j0 = 0; j0 < N_; j0 += 64) {
        for (int i = tid; i < 64 * 64; i += 256) {
            int kk = i >> 6, d = i & 63;
            int n = j0 + kk;
            float kv = 0.f, vv = 0.f;
            if (n < N_) {
                size_t base = ((size_t)(b * N_ + n)) * (3 * C_) + h * HD_ + d;
                kv = qkv[base + C_];
                vv = qkv[base + 2 * C_];
            }
            Kt[d][kk] = kv;
            Vs[kk][d] = vv;
        }
        __syncthreads();

        float s[8] = {0.f, 0.f, 0.f, 0.f, 0.f, 0.f, 0.f, 0.f};
#pragma unroll 8
        for (int d = 0; d < 64; d++) {
            float qv = Qs[r][d];
            float4 k0 = *reinterpret_cast<const float4*>(&Kt[d][cg * 8]);
            float4 k1 = *reinterpret_cast<const float4*>(&Kt[d][cg * 8 + 4]);
            s[0] += qv * k0.x; s[1] += qv * k0.y; s[2] += qv * k0.z; s[3] += qv * k0.w;
            s[4] += qv * k1.x; s[5] += qv * k1.y; s[6] += qv * k1.z; s[7] += qv * k1.w;
        }
#pragma unroll
        for (int jj = 0; jj < 8; jj++) {
            int col = cg * 8 + jj;
            S[r][col] = (j0 + col < N_) ? s[jj] * 0.125f : -1e30f;
        }
        __syncthreads();

        float mt = -1e30f;
#pragma unroll 8
        for (int c = 0; c < 64; c++) mt = fmaxf(mt, S[r][c]);
        float mn  = fmaxf(m, mt);
        float fac = __expf(m - mn);
        __syncthreads();

#pragma unroll
        for (int jj = 0; jj < 8; jj++) {
            int col = cg * 8 + jj;
            S[r][col] = __expf(S[r][col] - mn);
        }
        __syncthreads();

        float lsum = 0.f;
#pragma unroll
        for (int i = 0; i < 8; i++) acc[i] *= fac;
        for (int c = 0; c < 64; c++) {
            float p = S[r][c];
            lsum += p;
            float4 v0 = *reinterpret_cast<const float4*>(&Vs[c][cg * 8]);
            float4 v1 = *reinterpret_cast<const float4*>(&Vs[c][cg * 8 + 4]);
            acc[0] += p * v0.x; acc[1] += p * v0.y; acc[2] += p * v0.z; acc[3] += p * v0.w;
            acc[4] += p * v1.x; acc[5] += p * v1.y; acc[6] += p * v1.z; acc[7] += p * v1.w;
        }
        l = l * fac + lsum;
        m = mn;
        __syncthreads();
    }

    int n = qt * 32 + r;
    if (n < N_) {
        float inv = 1.f / l;
        float* o = out + ((size_t)(b * N_ + n)) * C_ + h * HD_ + cg * 8;
#pragma unroll
        for (int i = 0; i < 8; i++) o[i] = acc[i] * inv;
    }
}

// ------------------------------------------------------------------
// Launch
// ------------------------------------------------------------------
#define GEMM_SMEM (2 * (A_TILE + B_TILE) * (int)sizeof(float))   // 65536

extern "C" void kernel_launch(void* const* d_in, const int* in_sizes, int n_in,
                              void* d_out, int out_size) {
    const float* x      = (const float*)d_in[0];
    const float* ln1_g  = (const float*)d_in[1];
    const float* ln1_b  = (const float*)d_in[2];
    const float* w_qkv  = (const float*)d_in[3];
    const float* b_qkv  = (const float*)d_in[4];
    const float* w_proj = (const float*)d_in[5];
    const float* b_proj = (const float*)d_in[6];
    const float* ln2_g  = (const float*)d_in[7];
    const float* ln2_b  = (const float*)d_in[8];
    const float* w_fc1  = (const float*)d_in[9];
    const float* b_fc1  = (const float*)d_in[10];
    const float* w_fc2  = (const float*)d_in[11];
    const float* b_fc2  = (const float*)d_in[12];
    float* out = (float*)d_out;

    float *h, *qkv, *att, *x1, *fc1;
    cudaGetSymbolAddress((void**)&h,   g_h);
    cudaGetSymbolAddress((void**)&qkv, g_qkv);
    cudaGetSymbolAddress((void**)&att, g_att);
    cudaGetSymbolAddress((void**)&x1,  g_x1);
    cudaGetSymbolAddress((void**)&fc1, g_fc1);

    static bool attr_done = false;
    if (!attr_done) {
        cudaFuncSetAttribute(gemm_tc<EPI_BIAS>,
                             cudaFuncAttributeMaxDynamicSharedMemorySize, GEMM_SMEM);
        cudaFuncSetAttribute(gemm_tc<EPI_BIAS_RES>,
                             cudaFuncAttributeMaxDynamicSharedMemorySize, GEMM_SMEM);
        cudaFuncSetAttribute(gemm_tc<EPI_BIAS_GELU>,
                             cudaFuncAttributeMaxDynamicSharedMemorySize, GEMM_SMEM);
        attr_done = true;
    }

    const int MB = (M_ + 127) / 128;   // 73

    // 1) LN1
    ln_kernel<<<M_, 256>>>(x, ln1_g, ln1_b, h);
    // 2) QKV = h @ w_qkv + b_qkv     [9232 x 2304]
    gemm_tc<EPI_BIAS><<<dim3(3 * C_ / 128, MB), 256, GEMM_SMEM>>>(
        h, w_qkv, b_qkv, nullptr, qkv, M_, 3 * C_, C_);
    // 3) attention
    attn_kernel<<<dim3((N_ + 31) / 32, HEADS_, B_), 256>>>(qkv, att);
    // 4) x1 = x + att @ w_proj + b_proj
    gemm_tc<EPI_BIAS_RES><<<dim3(C_ / 128, MB), 256, GEMM_SMEM>>>(
        att, w_proj, b_proj, x, x1, M_, C_, C_);
    // 5) LN2
    ln_kernel<<<M_, 256>>>(x1, ln2_g, ln2_b, h);
    // 6) fc1 = gelu(h @ w_fc1 + b_fc1)   [9232 x 3072]
    gemm_tc<EPI_BIAS_GELU><<<dim3(HID_ / 128, MB), 256, GEMM_SMEM>>>(
        h, w_fc1, b_fc1, nullptr, fc1, M_, HID_, C_);
    // 7) out = x1 + fc1 @ w_fc2 + b_fc2
    gemm_tc<EPI_BIAS_RES><<<dim3(C_ / 128, MB), 256, GEMM_SMEM>>>(
        fc1, w_fc2, b_fc2, x1, out, M_, C_, HID_);
}

// round 4
// speedup vs baseline: 5.1032x; 3.2254x over previous
#include <cuda_runtime.h>
#include <cmath>
#include <cstdint>

// ------------------------------------------------------------------
// Problem constants
// ------------------------------------------------------------------
#define B_     16
#define N_     577
#define C_     768
#define HEADS_ 12
#define HD_    64
#define HID_   3072
#define M_     (B_ * N_)        // 9232 rows

// ------------------------------------------------------------------
// Static scratch
// ------------------------------------------------------------------
__device__ float g_h   [M_ * C_];
__device__ float g_qkv [M_ * 3 * C_];
__device__ float g_att [M_ * C_];
__device__ float g_x1  [M_ * C_];
__device__ float g_fc1 [M_ * HID_];

// ------------------------------------------------------------------
// LayerNorm
// ------------------------------------------------------------------
__global__ void ln_kernel(const float* __restrict__ x,
                          const float* __restrict__ g,
                          const float* __restrict__ b,
                          float* __restrict__ out) {
    int row = blockIdx.x;
    const float* xr = x + (size_t)row * C_;
    float sum = 0.f, sumsq = 0.f;
    for (int i = threadIdx.x; i < C_; i += blockDim.x) {
        float v = xr[i];
        sum += v; sumsq += v * v;
    }
    __shared__ float s1[8], s2[8];
    for (int o = 16; o; o >>= 1) {
        sum   += __shfl_down_sync(0xffffffffu, sum, o);
        sumsq += __shfl_down_sync(0xffffffffu, sumsq, o);
    }
    int wid = threadIdx.x >> 5, lid = threadIdx.x & 31;
    if (lid == 0) { s1[wid] = sum; s2[wid] = sumsq; }
    __syncthreads();
    if (wid == 0) {
        sum   = (lid < 8) ? s1[lid] : 0.f;
        sumsq = (lid < 8) ? s2[lid] : 0.f;
        for (int o = 4; o; o >>= 1) {
            sum   += __shfl_down_sync(0xffffffffu, sum, o);
            sumsq += __shfl_down_sync(0xffffffffu, sumsq, o);
        }
        if (lid == 0) { s1[0] = sum; s2[0] = sumsq; }
    }
    __syncthreads();
    float mu   = s1[0] * (1.f / C_);
    float var  = s2[0] * (1.f / C_) - mu * mu;
    float rstd = rsqrtf(var + 1e-5f);
    float* orow = out + (size_t)row * C_;
    for (int i = threadIdx.x; i < C_; i += blockDim.x)
        orow[i] = (xr[i] - mu) * rstd * g[i] + b[i];
}

// ------------------------------------------------------------------
// tf32 tensor-core helpers
// ------------------------------------------------------------------
__device__ __forceinline__ uint32_t cvt_tf32(float x) {
    uint32_t r;
    asm("cvt.rna.tf32.f32 %0, %1;" : "=r"(r) : "f"(x));
    return r;
}

__device__ __forceinline__ void mma_tf32(float& d0, float& d1, float& d2, float& d3,
                                         uint32_t a0, uint32_t a1, uint32_t a2, uint32_t a3,
                                         uint32_t b0, uint32_t b1) {
    asm volatile(
        "mma.sync.aligned.m16n8k8.row.col.f32.tf32.tf32.f32 "
        "{%0,%1,%2,%3}, {%4,%5,%6,%7}, {%8,%9}, {%0,%1,%2,%3};"
        : "+f"(d0), "+f"(d1), "+f"(d2), "+f"(d3)
        : "r"(a0), "r"(a1), "r"(a2), "r"(a3), "r"(b0), "r"(b1));
}

__device__ __forceinline__ void cp_async16(uint32_t dst_smem, const void* src, bool pred) {
    int sz = pred ? 16 : 0;
    asm volatile("cp.async.cg.shared.global [%0], [%1], 16, %2;"
                 :: "r"(dst_smem), "l"(src), "r"(sz));
}

// Fast exp on the FMA pipe: exp(x) = 2^(x*log2e), 5th-order poly + exponent splice.
// Valid for x <= 0 (softmax args); clamped at -80 so masked (-1e30) -> ~0.
__device__ __forceinline__ float fexp(float x) {
    x = fmaxf(x, -80.f);
    float y = x * 1.4426950408889634f;
    float t = y + 12582912.f;                 // round-to-nearest integer trick
    int   i = __float_as_int(t) << 23;        // integer part -> exponent offset
    float f = y - (t - 12582912.f);           // fractional part in [-0.5, 0.5]
    float p = 1.3333558146e-3f;
    p = fmaf(p, f, 9.6181291076e-3f);
    p = fmaf(p, f, 5.5504108665e-2f);
    p = fmaf(p, f, 2.4022650696e-1f);
    p = fmaf(p, f, 6.9314718056e-1f);
    p = fmaf(p, f, 1.0f);
    return __int_as_float(__float_as_int(p) + i);
}

// ------------------------------------------------------------------
// tf32 tensor-core GEMM (unchanged from R3)
// ------------------------------------------------------------------
#define EPI_BIAS      0
#define EPI_BIAS_RES  1
#define EPI_BIAS_GELU 2

#define A_TILE (128 * 32)
#define B_TILE (32 * 128)

template <int EPI>
__global__ __launch_bounds__(256)
void gemm_tc(const float* __restrict__ A, const float* __restrict__ Bm,
             const float* __restrict__ bias, const float* __restrict__ res,
             float* __restrict__ C, int M, int N, int K) {
    extern __shared__ float smem[];
    float* As = smem;               // [2][128][32]
    float* Bs = smem + 2 * A_TILE;  // [2][32][128]

    const int tid  = threadIdx.x;
    const int wid  = tid >> 5, lane = tid & 31;
    const int wm   = wid >> 2, wn = wid & 3;
    const int row0 = blockIdx.y * 128, col0 = blockIdx.x * 128;

    const int m_a  = tid >> 3;
    const int kg_a = (tid & 7) * 4;
    const int k_b  = tid >> 5;
    const int ng_b = (tid & 31) * 4;

    float acc[4][4][4];
#pragma unroll
    for (int i = 0; i < 4; i++)
#pragma unroll
        for (int j = 0; j < 4; j++)
#pragma unroll
            for (int t = 0; t < 4; t++) acc[i][j][t] = 0.f;

    const int nIter = K / 32;

    auto load_tiles = [&](int k0, int buf) {
        float* Ab = As + buf * A_TILE;
        float* Bb = Bs + buf * B_TILE;
#pragma unroll
        for (int p = 0; p < 4; p++) {
            int m   = m_a + p * 32;
            int row = row0 + m;
            uint32_t dst = (uint32_t)__cvta_generic_to_shared(
                Ab + m * 32 + (kg_a ^ (4 * (m & 7))));
            cp_async16(dst, A + (size_t)row * K + k0 + kg_a, row < M);
        }
#pragma unroll
        for (int p = 0; p < 4; p++) {
            int k = k_b + p * 8;
            uint32_t dst = (uint32_t)__cvta_generic_to_shared(
                Bb + k * 128 + (ng_b ^ (8 * (k & 3))));
            cp_async16(dst, Bm + (size_t)(k0 + k) * N + col0 + ng_b, true);
        }
        asm volatile("cp.async.commit_group;");
    };

    load_tiles(0, 0);

    const int fr = lane >> 2;
    const int fc = lane & 3;

    for (int it = 0; it < nIter; ++it) {
        if (it + 1 < nIter) {
            load_tiles((it + 1) * 32, (it + 1) & 1);
            asm volatile("cp.async.wait_group 1;");
        } else {
            asm volatile("cp.async.wait_group 0;");
        }
        __syncthreads();

        const float* Ab = As + (it & 1) * A_TILE;
        const float* Bb = Bs + (it & 1) * B_TILE;
        const int xa = 4 * fr;

#pragma unroll
        for (int ks = 0; ks < 4; ks++) {
            const int k0 = ks * 8 + fc;
            const int xb = 8 * fc;
            uint32_t af[4][4], bf[4][2];
#pragma unroll
            for (int mt = 0; mt < 4; mt++) {
                int m0 = wm * 64 + mt * 16 + fr;
                af[mt][0] = cvt_tf32(Ab[(m0)     * 32 + ((k0)     ^ xa)]);
                af[mt][1] = cvt_tf32(Ab[(m0 + 8) * 32 + ((k0)     ^ xa)]);
                af[mt][2] = cvt_tf32(Ab[(m0)     * 32 + ((k0 + 4) ^ xa)]);
                af[mt][3] = cvt_tf32(Ab[(m0 + 8) * 32 + ((k0 + 4) ^ xa)]);
            }
#pragma unroll
            for (int nt = 0; nt < 4; nt++) {
                int n0 = wn * 32 + nt * 8 + fr;
                bf[nt][0] = cvt_tf32(Bb[(k0)     * 128 + (n0 ^ xb)]);
                bf[nt][1] = cvt_tf32(Bb[(k0 + 4) * 128 + (n0 ^ xb)]);
            }
#pragma unroll
            for (int mt = 0; mt < 4; mt++)
#pragma unroll
                for (int nt = 0; nt < 4; nt++)
                    mma_tf32(acc[mt][nt][0], acc[mt][nt][1], acc[mt][nt][2], acc[mt][nt][3],
                             af[mt][0], af[mt][1], af[mt][2], af[mt][3],
                             bf[nt][0], bf[nt][1]);
        }
        __syncthreads();
    }

    const int c2 = fc * 2;
#pragma unroll
    for (int mt = 0; mt < 4; mt++) {
#pragma unroll
        for (int half = 0; half < 2; half++) {
            int row = row0 + wm * 64 + mt * 16 + fr + half * 8;
            if (row >= M) continue;
#pragma unroll
            for (int nt = 0; nt < 4; nt++) {
                int col = col0 + wn * 32 + nt * 8 + c2;
                float v0 = acc[mt][nt][half * 2 + 0] + bias[col];
                float v1 = acc[mt][nt][half * 2 + 1] + bias[col + 1];
                if (EPI == EPI_BIAS_RES) {
                    v0 += res[(size_t)row * N + col];
                    v1 += res[(size_t)row * N + col + 1];
                }
                if (EPI == EPI_BIAS_GELU) {
                    v0 = 0.5f * v0 * (1.f + erff(v0 * 0.70710678118654752f));
                    v1 = 0.5f * v1 * (1.f + erff(v1 * 0.70710678118654752f));
                }
                *reinterpret_cast<float2*>(&C[(size_t)row * N + col]) = make_float2(v0, v1);
            }
        }
    }
}

// ------------------------------------------------------------------
// Tensor-core flash attention (tf32 mma, fast-exp softmax)
// Block: 128 query rows x one (b,h). 8 warps, 16 rows/warp.
// Key tiles of 64. Smem (96KB):
//   Qs [128][64]  swizzle d ^ 4*(row&7)
//   Ks [ 64][64]  swizzle d ^ 4*(row&7)
//   Vs [ 64][64]  swizzle d ^ 8*(row&3)   (conflict-free b-frag column access)
//   Ps [8 warps][16][64] swizzle key ^ 4*(row&7)  (warp-private P buffer)
// ------------------------------------------------------------------
#define AQ_OFF 0
#define AK_OFF (128 * 64)
#define AV_OFF (AK_OFF + 64 * 64)
#define AP_OFF (AV_OFF + 64 * 64)
#define ATTN_SMEM ((AP_OFF + 8 * 16 * 64) * (int)sizeof(float))   // 96KB

__global__ __launch_bounds__(256, 2)
void attn_tc(const float* __restrict__ qkv, float* __restrict__ out) {
    extern __shared__ float sm[];
    float* Qs = sm + AQ_OFF;
    float* Ks = sm + AK_OFF;
    float* Vs = sm + AV_OFF;

    const int tid  = threadIdx.x;
    const int wid  = tid >> 5, lane = tid & 31;
    const int fr   = lane >> 2, fc = lane & 3;
    const int qt   = blockIdx.x, h = blockIdx.y, b = blockIdx.z;

    float* Ps = sm + AP_OFF + wid * (16 * 64);

    const float* qbase = qkv + (size_t)(b * N_) * (3 * C_) + h * HD_;

    // ---- stage Q tile (zero-filled beyond N_) ----
    {
        int r = tid >> 4;                 // 0..15 (+16*p)
        int c = (tid & 15) * 4;           // 0..60
#pragma unroll
        for (int p = 0; p < 8; p++) {
            int rr = r + p * 16;
            int n  = qt * 128 + rr;
            uint32_t dst = (uint32_t)__cvta_generic_to_shared(
                Qs + rr * 64 + (c ^ (4 * (rr & 7))));
            cp_async16(dst, qbase + (size_t)n * (3 * C_) + c, n < N_);
        }
    }

    // ---- K/V tile loader ----
    auto load_kv = [&](int j0) {
        int r = tid >> 4;
        int c = (tid & 15) * 4;
#pragma unroll
        for (int p = 0; p < 4; p++) {
            int rr = r + p * 16;
            int n  = j0 + rr;
            const float* src = qbase + (size_t)n * (3 * C_) + c;
            uint32_t dk = (uint32_t)__cvta_generic_to_shared(
                Ks + rr * 64 + (c ^ (4 * (rr & 7))));
            cp_async16(dk, src + C_, n < N_);
            uint32_t dv = (uint32_t)__cvta_generic_to_shared(
                Vs + rr * 64 + (c ^ (8 * (rr & 3))));
            cp_async16(dv, src + 2 * C_, n < N_);
        }
        asm volatile("cp.async.commit_group;");
    };

    load_kv(0);
    asm volatile("cp.async.wait_group 0;");
    __syncthreads();

    const int mrow = wid * 16 + fr;       // this thread's row (and +8)
    const int xa   = 4 * fr;

    float O[8][4];
#pragma unroll
    for (int nf = 0; nf < 8; nf++)
#pragma unroll
        for (int t = 0; t < 4; t++) O[nf][t] = 0.f;
    float m0 = -1e30f, m1 = -1e30f, l0 = 0.f, l1 = 0.f;

    const int NT = (N_ + 63) / 64;        // 10

    for (int jt = 0; jt < NT; jt++) {
        const int j0 = jt * 64;

        // ---- S = Q K^T  (16 x 64 per warp) ----
        float S[8][4];
#pragma unroll
        for (int nf = 0; nf < 8; nf++)
#pragma unroll
            for (int t = 0; t < 4; t++) S[nf][t] = 0.f;

#pragma unroll
        for (int ks = 0; ks < 8; ks++) {
            const int k0 = ks * 8 + fc;
            uint32_t a0 = cvt_tf32(Qs[(mrow)     * 64 + ((k0)     ^ xa)]);
            uint32_t a1 = cvt_tf32(Qs[(mrow + 8) * 64 + ((k0)     ^ xa)]);
            uint32_t a2 = cvt_tf32(Qs[(mrow)     * 64 + ((k0 + 4) ^ xa)]);
            uint32_t a3 = cvt_tf32(Qs[(mrow + 8) * 64 + ((k0 + 4) ^ xa)]);
#pragma unroll
            for (int nf = 0; nf < 8; nf++) {
                int n0 = nf * 8 + fr;
                uint32_t b0 = cvt_tf32(Ks[n0 * 64 + ((k0)     ^ (4 * fr))]);
                uint32_t b1 = cvt_tf32(Ks[n0 * 64 + ((k0 + 4) ^ (4 * fr))]);
                mma_tf32(S[nf][0], S[nf][1], S[nf][2], S[nf][3],
                         a0, a1, a2, a3, b0, b1);
            }
        }

        // ---- online softmax ----
        float mt0 = -1e30f, mt1 = -1e30f;
#pragma unroll
        for (int nf = 0; nf < 8; nf++) {
            int jb = j0 + nf * 8 + 2 * fc;
            float s0 = S[nf][0] * 0.125f, s1 = S[nf][1] * 0.125f;
            float s2 = S[nf][2] * 0.125f, s3 = S[nf][3] * 0.125f;
            if (jb     >= N_) { s0 = -1e30f; s2 = -1e30f; }
            if (jb + 1 >= N_) { s1 = -1e30f; s3 = -1e30f; }
            S[nf][0] = s0; S[nf][1] = s1; S[nf][2] = s2; S[nf][3] = s3;
            mt0 = fmaxf(mt0, fmaxf(s0, s1));
            mt1 = fmaxf(mt1, fmaxf(s2, s3));
        }
        mt0 = fmaxf(mt0, __shfl_xor_sync(0xffffffffu, mt0, 1));
        mt0 = fmaxf(mt0, __shfl_xor_sync(0xffffffffu, mt0, 2));
        mt1 = fmaxf(mt1, __shfl_xor_sync(0xffffffffu, mt1, 1));
        mt1 = fmaxf(mt1, __shfl_xor_sync(0xffffffffu, mt1, 2));

        float mn0 = fmaxf(m0, mt0), mn1 = fmaxf(m1, mt1);
        float f0 = fexp(m0 - mn0),  f1 = fexp(m1 - mn1);
        m0 = mn0; m1 = mn1;
        l0 *= f0; l1 *= f1;

        float ls0 = 0.f, ls1 = 0.f;
#pragma unroll
        for (int nf = 0; nf < 8; nf++) {
            float p0 = fexp(S[nf][0] - mn0);
            float p1 = fexp(S[nf][1] - mn0);
            float p2 = fexp(S[nf][2] - mn1);
            float p3 = fexp(S[nf][3] - mn1);
            ls0 += p0 + p1; ls1 += p2 + p3;
            // rescale O
            O[nf][0] *= f0; O[nf][1] *= f0; O[nf][2] *= f1; O[nf][3] *= f1;
            // store P to warp-private smem (A-frag swizzle)
            int colb = nf * 8 + 2 * fc;
            *reinterpret_cast<float2*>(&Ps[(fr)     * 64 + (colb ^ xa)]) = make_float2(p0, p1);
            *reinterpret_cast<float2*>(&Ps[(fr + 8) * 64 + (colb ^ xa)]) = make_float2(p2, p3);
        }
        l0 += ls0; l1 += ls1;
        __syncwarp();

        // ---- O += P V  (k-dim = 64 keys) ----
#pragma unroll
        for (int ks = 0; ks < 8; ks++) {
            const int k0 = ks * 8 + fc;
            uint32_t a0 = cvt_tf32(Ps[(fr)     * 64 + ((k0)     ^ xa)]);
            uint32_t a1 = cvt_tf32(Ps[(fr + 8) * 64 + ((k0)     ^ xa)]);
            uint32_t a2 = cvt_tf32(Ps[(fr)     * 64 + ((k0 + 4) ^ xa)]);
            uint32_t a3 = cvt_tf32(Ps[(fr + 8) * 64 + ((k0 + 4) ^ xa)]);
            const int xb = 8 * fc;
#pragma unroll
            for (int nf = 0; nf < 8; nf++) {
                int n0 = nf * 8 + fr;
                uint32_t b0 = cvt_tf32(Vs[(k0)     * 64 + (n0 ^ xb)]);
                uint32_t b1 = cvt_tf32(Vs[(k0 + 4) * 64 + (n0 ^ xb)]);
                mma_tf32(O[nf][0], O[nf][1], O[nf][2], O[nf][3],
                         a0, a1, a2, a3, b0, b1);
            }
        }

        __syncthreads();                      // done reading Ks/Vs
        if (jt + 1 < NT) {
            load_kv(j0 + 64);
            asm volatile("cp.async.wait_group 0;");
            __syncthreads();
        }
    }

    // ---- finalize ----
    l0 += __shfl_xor_sync(0xffffffffu, l0, 1);
    l0 += __shfl_xor_sync(0xffffffffu, l0, 2);
    l1 += __shfl_xor_sync(0xffffffffu, l1, 1);
    l1 += __shfl_xor_sync(0xffffffffu, l1, 2);
    float inv0 = 1.f / l0, inv1 = 1.f / l1;

    int n0r = qt * 128 + mrow;
    int n1r = n0r + 8;
    float* obase = out + (size_t)(b * N_) * C_ + h * HD_;
    if (n0r < N_) {
#pragma unroll
        for (int nf = 0; nf < 8; nf++) {
            int col = nf * 8 + 2 * fc;
            *reinterpret_cast<float2*>(&obase[(size_t)n0r * C_ + col]) =
                make_float2(O[nf][0] * inv0, O[nf][1] * inv0);
        }
    }
    if (n1r < N_) {
#pragma unroll
        for (int nf = 0; nf < 8; nf++) {
            int col = nf * 8 + 2 * fc;
            *reinterpret_cast<float2*>(&obase[(size_t)n1r * C_ + col]) =
                make_float2(O[nf][2] * inv1, O[nf][3] * inv1);
        }
    }
}

// ------------------------------------------------------------------
// Launch
// ------------------------------------------------------------------
#define GEMM_SMEM (2 * (A_TILE + B_TILE) * (int)sizeof(float))   // 65536

extern "C" void kernel_launch(void* const* d_in, const int* in_sizes, int n_in,
                              void* d_out, int out_size) {
    const float* x      = (const float*)d_in[0];
    const float* ln1_g  = (const float*)d_in[1];
    const float* ln1_b  = (const float*)d_in[2];
    const float* w_qkv  = (const float*)d_in[3];
    const float* b_qkv  = (const float*)d_in[4];
    const float* w_proj = (const float*)d_in[5];
    const float* b_proj = (const float*)d_in[6];
    const float* ln2_g  = (const float*)d_in[7];
    const float* ln2_b  = (const float*)d_in[8];
    const float* w_fc1  = (const float*)d_in[9];
    const float* b_fc1  = (const float*)d_in[10];
    const float* w_fc2  = (const float*)d_in[11];
    const float* b_fc2  = (const float*)d_in[12];
    float* out = (float*)d_out;

    float *h, *qkv, *att, *x1, *fc1;
    cudaGetSymbolAddress((void**)&h,   g_h);
    cudaGetSymbolAddress((void**)&qkv, g_qkv);
    cudaGetSymbolAddress((void**)&att, g_att);
    cudaGetSymbolAddress((void**)&x1,  g_x1);
    cudaGetSymbolAddress((void**)&fc1, g_fc1);

    static bool attr_done = false;
    if (!attr_done) {
        cudaFuncSetAttribute(gemm_tc<EPI_BIAS>,
                             cudaFuncAttributeMaxDynamicSharedMemorySize, GEMM_SMEM);
        cudaFuncSetAttribute(gemm_tc<EPI_BIAS_RES>,
                             cudaFuncAttributeMaxDynamicSharedMemorySize, GEMM_SMEM);
        cudaFuncSetAttribute(gemm_tc<EPI_BIAS_GELU>,
                             cudaFuncAttributeMaxDynamicSharedMemorySize, GEMM_SMEM);
        cudaFuncSetAttribute(attn_tc,
                             cudaFuncAttributeMaxDynamicSharedMemorySize, ATTN_SMEM);
        attr_done = true;
    }

    const int MB = (M_ + 127) / 128;   // 73

    // 1) LN1
    ln_kernel<<<M_, 256>>>(x, ln1_g, ln1_b, h);
    // 2) QKV = h @ w_qkv + b_qkv     [9232 x 2304]
    gemm_tc<EPI_BIAS><<<dim3(3 * C_ / 128, MB), 256, GEMM_SMEM>>>(
        h, w_qkv, b_qkv, nullptr, qkv, M_, 3 * C_, C_);
    // 3) attention (tensor-core flash)
    attn_tc<<<dim3((N_ + 127) / 128, HEADS_, B_), 256, ATTN_SMEM>>>(qkv, att);
    // 4) x1 = x + att @ w_proj + b_proj
    gemm_tc<EPI_BIAS_RES><<<dim3(C_ / 128, MB), 256, GEMM_SMEM>>>(
        att, w_proj, b_proj, x, x1, M_, C_, C_);
    // 5) LN2
    ln_kernel<<<M_, 256>>>(x1, ln2_g, ln2_b, h);
    // 6) fc1 = gelu(h @ w_fc1 + b_fc1)   [9232 x 3072]
    gemm_tc<EPI_BIAS_GELU><<<dim3(HID_ / 128, MB), 256, GEMM_SMEM>>>(
        h, w_fc1, b_fc1, nullptr, fc1, M_, HID_, C_);
    // 7) out = x1 + fc1 @ w_fc2 + b_fc2
    gemm_tc<EPI_BIAS_RES><<<dim3(C_ / 128, MB), 256, GEMM_SMEM>>>(
        fc1, w_fc2, b_fc2, x1, out, M_, C_, HID_);
}

// round 6
// speedup vs baseline: 5.9767x; 1.1712x over previous
#include <cuda_runtime.h>
#include <cmath>
#include <cstdint>

// ------------------------------------------------------------------
// Problem constants
// ------------------------------------------------------------------
#define B_     16
#define N_     577
#define C_     768
#define HEADS_ 12
#define HD_    64
#define HID_   3072
#define M_     (B_ * N_)        // 9232 rows

// ------------------------------------------------------------------
// Static scratch
// ------------------------------------------------------------------
__device__ float g_h   [M_ * C_];
__device__ float g_qkv [M_ * 3 * C_];
__device__ float g_att [M_ * C_];
__device__ float g_x1  [M_ * C_];
__device__ float g_fc1 [M_ * HID_];

// ------------------------------------------------------------------
// LayerNorm
// ------------------------------------------------------------------
__global__ void ln_kernel(const float* __restrict__ x,
                          const float* __restrict__ g,
                          const float* __restrict__ b,
                          float* __restrict__ out) {
    int row = blockIdx.x;
    const float* xr = x + (size_t)row * C_;
    float sum = 0.f, sumsq = 0.f;
    for (int i = threadIdx.x; i < C_; i += blockDim.x) {
        float v = xr[i];
        sum += v; sumsq += v * v;
    }
    __shared__ float s1[8], s2[8];
    for (int o = 16; o; o >>= 1) {
        sum   += __shfl_down_sync(0xffffffffu, sum, o);
        sumsq += __shfl_down_sync(0xffffffffu, sumsq, o);
    }
    int wid = threadIdx.x >> 5, lid = threadIdx.x & 31;
    if (lid == 0) { s1[wid] = sum; s2[wid] = sumsq; }
    __syncthreads();
    if (wid == 0) {
        sum   = (lid < 8) ? s1[lid] : 0.f;
        sumsq = (lid < 8) ? s2[lid] : 0.f;
        for (int o = 4; o; o >>= 1) {
            sum   += __shfl_down_sync(0xffffffffu, sum, o);
            sumsq += __shfl_down_sync(0xffffffffu, sumsq, o);
        }
        if (lid == 0) { s1[0] = sum; s2[0] = sumsq; }
    }
    __syncthreads();
    float mu   = s1[0] * (1.f / C_);
    float var  = s2[0] * (1.f / C_) - mu * mu;
    float rstd = rsqrtf(var + 1e-5f);
    float* orow = out + (size_t)row * C_;
    for (int i = threadIdx.x; i < C_; i += blockDim.x)
        orow[i] = (xr[i] - mu) * rstd * g[i] + b[i];
}

// ------------------------------------------------------------------
// tensor-core helpers
// ------------------------------------------------------------------
// Raw fp32 bits as tf32 operand (HW ignores low mantissa bits; truncation
// rounding). Saves the cvt.rna.tf32 issue slot per fragment element.
#define TFRAW(x) __float_as_uint(x)

__device__ __forceinline__ void mma_tf32(float& d0, float& d1, float& d2, float& d3,
                                         uint32_t a0, uint32_t a1, uint32_t a2, uint32_t a3,
                                         uint32_t b0, uint32_t b1) {
    asm volatile(
        "mma.sync.aligned.m16n8k8.row.col.f32.tf32.tf32.f32 "
        "{%0,%1,%2,%3}, {%4,%5,%6,%7}, {%8,%9}, {%0,%1,%2,%3};"
        : "+f"(d0), "+f"(d1), "+f"(d2), "+f"(d3)
        : "r"(a0), "r"(a1), "r"(a2), "r"(a3), "r"(b0), "r"(b1));
}

__device__ __forceinline__ void cp_async16(uint32_t dst_smem, const void* src, bool pred) {
    int sz = pred ? 16 : 0;
    asm volatile("cp.async.cg.shared.global [%0], [%1], 16, %2;"
                 :: "r"(dst_smem), "l"(src), "r"(sz));
}

// Fast exp on the FMA pipe (valid for x <= 0; masked -1e30 -> ~0).
__device__ __forceinline__ float fexp(float x) {
    x = fmaxf(x, -80.f);
    float y = x * 1.4426950408889634f;
    float t = y + 12582912.f;
    int   i = __float_as_int(t) << 23;
    float f = y - (t - 12582912.f);
    float p = 1.3333558146e-3f;
    p = fmaf(p, f, 9.6181291076e-3f);
    p = fmaf(p, f, 5.5504108665e-2f);
    p = fmaf(p, f, 2.4022650696e-1f);
    p = fmaf(p, f, 6.9314718056e-1f);
    p = fmaf(p, f, 1.0f);
    return __int_as_float(__float_as_int(p) + i);
}

// ------------------------------------------------------------------
// tf32 tensor-core GEMM: C = epi(A[MxK] @ B[KxN] + bias [, + res])
// 128x128x32 tiles, 8 warps (2x4), warp tile 64x32 (4x4 m16n8k8 frags).
// XOR-swizzled smem -> conflict-free fragment loads.
// cp.async double buffer, 64KB dynamic smem.
// ------------------------------------------------------------------
#define EPI_BIAS      0
#define EPI_BIAS_RES  1
#define EPI_BIAS_GELU 2

#define A_TILE (128 * 32)
#define B_TILE (32 * 128)

template <int EPI>
__global__ __launch_bounds__(256)
void gemm_tc(const float* __restrict__ A, const float* __restrict__ Bm,
             const float* __restrict__ bias, const float* __restrict__ res,
             float* __restrict__ C, int M, int N, int K) {
    extern __shared__ float smem[];
    float* As = smem;               // [2][128][32]
    float* Bs = smem + 2 * A_TILE;  // [2][32][128]

    const int tid  = threadIdx.x;
    const int wid  = tid >> 5, lane = tid & 31;
    const int wm   = wid >> 2, wn = wid & 3;
    const int row0 = blockIdx.y * 128, col0 = blockIdx.x * 128;

    const int m_a  = tid >> 3;
    const int kg_a = (tid & 7) * 4;
    const int k_b  = tid >> 5;
    const int ng_b = (tid & 31) * 4;

    float acc[4][4][4];
#pragma unroll
    for (int i = 0; i < 4; i++)
#pragma unroll
        for (int j = 0; j < 4; j++)
#pragma unroll
            for (int t = 0; t < 4; t++) acc[i][j][t] = 0.f;

    const int nIter = K / 32;

    auto load_tiles = [&](int k0, int buf) {
        float* Ab = As + buf * A_TILE;
        float* Bb = Bs + buf * B_TILE;
#pragma unroll
        for (int p = 0; p < 4; p++) {
            int m   = m_a + p * 32;
            int row = row0 + m;
            uint32_t dst = (uint32_t)__cvta_generic_to_shared(
                Ab + m * 32 + (kg_a ^ (4 * (m & 7))));
            cp_async16(dst, A + (size_t)row * K + k0 + kg_a, row < M);
        }
#pragma unroll
        for (int p = 0; p < 4; p++) {
            int k = k_b + p * 8;
            uint32_t dst = (uint32_t)__cvta_generic_to_shared(
                Bb + k * 128 + (ng_b ^ (8 * (k & 3))));
            cp_async16(dst, Bm + (size_t)(k0 + k) * N + col0 + ng_b, true);
        }
        asm volatile("cp.async.commit_group;");
    };

    load_tiles(0, 0);

    const int fr = lane >> 2;
    const int fc = lane & 3;

    for (int it = 0; it < nIter; ++it) {
        if (it + 1 < nIter) {
            load_tiles((it + 1) * 32, (it + 1) & 1);
            asm volatile("cp.async.wait_group 1;");
        } else {
            asm volatile("cp.async.wait_group 0;");
        }
        __syncthreads();

        const float* Ab = As + (it & 1) * A_TILE;
        const float* Bb = Bs + (it & 1) * B_TILE;
        const int xa = 4 * fr;

#pragma unroll
        for (int ks = 0; ks < 4; ks++) {
            const int k0 = ks * 8 + fc;
            const int xb = 8 * fc;
            uint32_t af[4][4], bf[4][2];
#pragma unroll
            for (int mt = 0; mt < 4; mt++) {
                int m0 = wm * 64 + mt * 16 + fr;
                af[mt][0] = TFRAW(Ab[(m0)     * 32 + ((k0)     ^ xa)]);
                af[mt][1] = TFRAW(Ab[(m0 + 8) * 32 + ((k0)     ^ xa)]);
                af[mt][2] = TFRAW(Ab[(m0)     * 32 + ((k0 + 4) ^ xa)]);
                af[mt][3] = TFRAW(Ab[(m0 + 8) * 32 + ((k0 + 4) ^ xa)]);
            }
#pragma unroll
            for (int nt = 0; nt < 4; nt++) {
                int n0 = wn * 32 + nt * 8 + fr;
                bf[nt][0] = TFRAW(Bb[(k0)     * 128 + (n0 ^ xb)]);
                bf[nt][1] = TFRAW(Bb[(k0 + 4) * 128 + (n0 ^ xb)]);
            }
#pragma unroll
            for (int mt = 0; mt < 4; mt++)
#pragma unroll
                for (int nt = 0; nt < 4; nt++)
                    mma_tf32(acc[mt][nt][0], acc[mt][nt][1], acc[mt][nt][2], acc[mt][nt][3],
                             af[mt][0], af[mt][1], af[mt][2], af[mt][3],
                             bf[nt][0], bf[nt][1]);
        }
        __syncthreads();
    }

    const int c2 = fc * 2;
#pragma unroll
    for (int mt = 0; mt < 4; mt++) {
#pragma unroll
        for (int half = 0; half < 2; half++) {
            int row = row0 + wm * 64 + mt * 16 + fr + half * 8;
            if (row >= M) continue;
#pragma unroll
            for (int nt = 0; nt < 4; nt++) {
                int col = col0 + wn * 32 + nt * 8 + c2;
                float v0 = acc[mt][nt][half * 2 + 0] + bias[col];
                float v1 = acc[mt][nt][half * 2 + 1] + bias[col + 1];
                if (EPI == EPI_BIAS_RES) {
                    v0 += res[(size_t)row * N + col];
                    v1 += res[(size_t)row * N + col + 1];
                }
                if (EPI == EPI_BIAS_GELU) {
                    v0 = 0.5f * v0 * (1.f + erff(v0 * 0.70710678118654752f));
                    v1 = 0.5f * v1 * (1.f + erff(v1 * 0.70710678118654752f));
                }
                *reinterpret_cast<float2*>(&C[(size_t)row * N + col]) = make_float2(v0, v1);
            }
        }
    }
}

// ------------------------------------------------------------------
// Tensor-core flash attention (tf32 mma, fast-exp softmax)
// ------------------------------------------------------------------
#define AQ_OFF 0
#define AK_OFF (128 * 64)
#define AV_OFF (AK_OFF + 64 * 64)
#define AP_OFF (AV_OFF + 64 * 64)
#define ATTN_SMEM ((AP_OFF + 8 * 16 * 64) * (int)sizeof(float))   // 96KB

__global__ __launch_bounds__(256, 2)
void attn_tc(const float* __restrict__ qkv, float* __restrict__ out) {
    extern __shared__ float sm[];
    float* Qs = sm + AQ_OFF;
    float* Ks = sm + AK_OFF;
    float* Vs = sm + AV_OFF;

    const int tid  = threadIdx.x;
    const int wid  = tid >> 5, lane = tid & 31;
    const int fr   = lane >> 2, fc = lane & 3;
    const int qt   = blockIdx.x, h = blockIdx.y, b = blockIdx.z;

    float* Ps = sm + AP_OFF + wid * (16 * 64);

    const float* qbase = qkv + (size_t)(b * N_) * (3 * C_) + h * HD_;

    {
        int r = tid >> 4;
        int c = (tid & 15) * 4;
#pragma unroll
        for (int p = 0; p < 8; p++) {
            int rr = r + p * 16;
            int n  = qt * 128 + rr;
            uint32_t dst = (uint32_t)__cvta_generic_to_shared(
                Qs + rr * 64 + (c ^ (4 * (rr & 7))));
            cp_async16(dst, qbase + (size_t)n * (3 * C_) + c, n < N_);
        }
    }

    auto load_kv = [&](int j0) {
        int r = tid >> 4;
        int c = (tid & 15) * 4;
#pragma unroll
        for (int p = 0; p < 4; p++) {
            int rr = r + p * 16;
            int n  = j0 + rr;
            const float* src = qbase + (size_t)n * (3 * C_) + c;
            uint32_t dk = (uint32_t)__cvta_generic_to_shared(
                Ks + rr * 64 + (c ^ (4 * (rr & 7))));
            cp_async16(dk, src + C_, n < N_);
            uint32_t dv = (uint32_t)__cvta_generic_to_shared(
                Vs + rr * 64 + (c ^ (8 * (rr & 3))));
            cp_async16(dv, src + 2 * C_, n < N_);
        }
        asm volatile("cp.async.commit_group;");
    };

    load_kv(0);
    asm volatile("cp.async.wait_group 0;");
    __syncthreads();

    const int mrow = wid * 16 + fr;
    const int xa   = 4 * fr;

    float O[8][4];
#pragma unroll
    for (int nf = 0; nf < 8; nf++)
#pragma unroll
        for (int t = 0; t < 4; t++) O[nf][t] = 0.f;
    float m0 = -1e30f, m1 = -1e30f, l0 = 0.f, l1 = 0.f;

    const int NT = (N_ + 63) / 64;

    for (int jt = 0; jt < NT; jt++) {
        const int j0 = jt * 64;

        float S[8][4];
#pragma unroll
        for (int nf = 0; nf < 8; nf++)
#pragma unroll
            for (int t = 0; t < 4; t++) S[nf][t] = 0.f;

#pragma unroll
        for (int ks = 0; ks < 8; ks++) {
            const int k0 = ks * 8 + fc;
            uint32_t a0 = TFRAW(Qs[(mrow)     * 64 + ((k0)     ^ xa)]);
            uint32_t a1 = TFRAW(Qs[(mrow + 8) * 64 + ((k0)     ^ xa)]);
            uint32_t a2 = TFRAW(Qs[(mrow)     * 64 + ((k0 + 4) ^ xa)]);
            uint32_t a3 = TFRAW(Qs[(mrow + 8) * 64 + ((k0 + 4) ^ xa)]);
#pragma unroll
            for (int nf = 0; nf < 8; nf++) {
                int n0 = nf * 8 + fr;
                uint32_t b0 = TFRAW(Ks[n0 * 64 + ((k0)     ^ (4 * fr))]);
                uint32_t b1 = TFRAW(Ks[n0 * 64 + ((k0 + 4) ^ (4 * fr))]);
                mma_tf32(S[nf][0], S[nf][1], S[nf][2], S[nf][3],
                         a0, a1, a2, a3, b0, b1);
            }
        }

        float mt0 = -1e30f, mt1 = -1e30f;
#pragma unroll
        for (int nf = 0; nf < 8; nf++) {
            int jb = j0 + nf * 8 + 2 * fc;
            float s0 = S[nf][0] * 0.125f, s1 = S[nf][1] * 0.125f;
            float s2 = S[nf][2] * 0.125f, s3 = S[nf][3] * 0.125f;
            if (jb     >= N_) { s0 = -1e30f; s2 = -1e30f; }
            if (jb + 1 >= N_) { s1 = -1e30f; s3 = -1e30f; }
            S[nf][0] = s0; S[nf][1] = s1; S[nf][2] = s2; S[nf][3] = s3;
            mt0 = fmaxf(mt0, fmaxf(s0, s1));
            mt1 = fmaxf(mt1, fmaxf(s2, s3));
        }
        mt0 = fmaxf(mt0, __shfl_xor_sync(0xffffffffu, mt0, 1));
        mt0 = fmaxf(mt0, __shfl_xor_sync(0xffffffffu, mt0, 2));
        mt1 = fmaxf(mt1, __shfl_xor_sync(0xffffffffu, mt1, 1));
        mt1 = fmaxf(mt1, __shfl_xor_sync(0xffffffffu, mt1, 2));

        float mn0 = fmaxf(m0, mt0), mn1 = fmaxf(m1, mt1);
        float f0 = fexp(m0 - mn0),  f1 = fexp(m1 - mn1);
        m0 = mn0; m1 = mn1;
        l0 *= f0; l1 *= f1;

        float ls0 = 0.f, ls1 = 0.f;
#pragma unroll
        for (int nf = 0; nf < 8; nf++) {
            float p0 = fexp(S[nf][0] - mn0);
            float p1 = fexp(S[nf][1] - mn0);
            float p2 = fexp(S[nf][2] - mn1);
            float p3 = fexp(S[nf][3] - mn1);
            ls0 += p0 + p1; ls1 += p2 + p3;
            O[nf][0] *= f0; O[nf][1] *= f0; O[nf][2] *= f1; O[nf][3] *= f1;
            int colb = nf * 8 + 2 * fc;
            *reinterpret_cast<float2*>(&Ps[(fr)     * 64 + (colb ^ xa)]) = make_float2(p0, p1);
            *reinterpret_cast<float2*>(&Ps[(fr + 8) * 64 + (colb ^ xa)]) = make_float2(p2, p3);
        }
        l0 += ls0; l1 += ls1;
        __syncwarp();

#pragma unroll
        for (int ks = 0; ks < 8; ks++) {
            const int k0 = ks * 8 + fc;
            uint32_t a0 = TFRAW(Ps[(fr)     * 64 + ((k0)     ^ xa)]);
            uint32_t a1 = TFRAW(Ps[(fr + 8) * 64 + ((k0)     ^ xa)]);
            uint32_t a2 = TFRAW(Ps[(fr)     * 64 + ((k0 + 4) ^ xa)]);
            uint32_t a3 = TFRAW(Ps[(fr + 8) * 64 + ((k0 + 4) ^ xa)]);
            const int xb = 8 * fc;
#pragma unroll
            for (int nf = 0; nf < 8; nf++) {
                int n0 = nf * 8 + fr;
                uint32_t b0 = TFRAW(Vs[(k0)     * 64 + (n0 ^ xb)]);
                uint32_t b1 = TFRAW(Vs[(k0 + 4) * 64 + (n0 ^ xb)]);
                mma_tf32(O[nf][0], O[nf][1], O[nf][2], O[nf][3],
                         a0, a1, a2, a3, b0, b1);
            }
        }

        __syncthreads();
        if (jt + 1 < NT) {
            load_kv(j0 + 64);
            asm volatile("cp.async.wait_group 0;");
            __syncthreads();
        }
    }

    l0 += __shfl_xor_sync(0xffffffffu, l0, 1);
    l0 += __shfl_xor_sync(0xffffffffu, l0, 2);
    l1 += __shfl_xor_sync(0xffffffffu, l1, 1);
    l1 += __shfl_xor_sync(0xffffffffu, l1, 2);
    float inv0 = 1.f / l0, inv1 = 1.f / l1;

    int n0r = qt * 128 + mrow;
    int n1r = n0r + 8;
    float* obase = out + (size_t)(b * N_) * C_ + h * HD_;
    if (n0r < N_) {
#pragma unroll
        for (int nf = 0; nf < 8; nf++) {
            int col = nf * 8 + 2 * fc;
            *reinterpret_cast<float2*>(&obase[(size_t)n0r * C_ + col]) =
                make_float2(O[nf][0] * inv0, O[nf][1] * inv0);
        }
    }
    if (n1r < N_) {
#pragma unroll
        for (int nf = 0; nf < 8; nf++) {
            int col = nf * 8 + 2 * fc;
            *reinterpret_cast<float2*>(&obase[(size_t)n1r * C_ + col]) =
                make_float2(O[nf][2] * inv1, O[nf][3] * inv1);
        }
    }
}

// ------------------------------------------------------------------
// Launch
// ------------------------------------------------------------------
#define GEMM_SMEM (2 * (A_TILE + B_TILE) * (int)sizeof(float))   // 65536

extern "C" void kernel_launch(void* const* d_in, const int* in_sizes, int n_in,
                              void* d_out, int out_size) {
    const float* x      = (const float*)d_in[0];
    const float* ln1_g  = (const float*)d_in[1];
    const float* ln1_b  = (const float*)d_in[2];
    const float* w_qkv  = (const float*)d_in[3];
    const float* b_qkv  = (const float*)d_in[4];
    const float* w_proj = (const float*)d_in[5];
    const float* b_proj = (const float*)d_in[6];
    const float* ln2_g  = (const float*)d_in[7];
    const float* ln2_b  = (const float*)d_in[8];
    const float* w_fc1  = (const float*)d_in[9];
    const float* b_fc1  = (const float*)d_in[10];
    const float* w_fc2  = (const float*)d_in[11];
    const float* b_fc2  = (const float*)d_in[12];
    float* out = (float*)d_out;

    float *h, *qkv, *att, *x1, *fc1;
    cudaGetSymbolAddress((void**)&h,   g_h);
    cudaGetSymbolAddress((void**)&qkv, g_qkv);
    cudaGetSymbolAddress((void**)&att, g_att);
    cudaGetSymbolAddress((void**)&x1,  g_x1);
    cudaGetSymbolAddress((void**)&fc1, g_fc1);

    static bool attr_done = false;
    if (!attr_done) {
        cudaFuncSetAttribute(gemm_tc<EPI_BIAS>,
                             cudaFuncAttributeMaxDynamicSharedMemorySize, GEMM_SMEM);
        cudaFuncSetAttribute(gemm_tc<EPI_BIAS_RES>,
                             cudaFuncAttributeMaxDynamicSharedMemorySize, GEMM_SMEM);
        cudaFuncSetAttribute(gemm_tc<EPI_BIAS_GELU>,
                             cudaFuncAttributeMaxDynamicSharedMemorySize, GEMM_SMEM);
        cudaFuncSetAttribute(attn_tc,
                             cudaFuncAttributeMaxDynamicSharedMemorySize, ATTN_SMEM);
        attr_done = true;
    }

    const int MB = (M_ + 127) / 128;   // 73

    // 1) LN1
    ln_kernel<<<M_, 256>>>(x, ln1_g, ln1_b, h);
    // 2) QKV = h @ w_qkv + b_qkv
    gemm_tc<EPI_BIAS><<<dim3(3 * C_ / 128, MB), 256, GEMM_SMEM>>>(
        h, w_qkv, b_qkv, nullptr, qkv, M_, 3 * C_, C_);
    // 3) attention (tensor-core flash)
    attn_tc<<<dim3((N_ + 127) / 128, HEADS_, B_), 256, ATTN_SMEM>>>(qkv, att);
    // 4) x1 = x + att @ w_proj + b_proj
    gemm_tc<EPI_BIAS_RES><<<dim3(C_ / 128, MB), 256, GEMM_SMEM>>>(
        att, w_proj, b_proj, x, x1, M_, C_, C_);
    // 5) LN2
    ln_kernel<<<M_, 256>>>(x1, ln2_g, ln2_b, h);
    // 6) fc1 = gelu(h @ w_fc1 + b_fc1)
    gemm_tc<EPI_BIAS_GELU><<<dim3(HID_ / 128, MB), 256, GEMM_SMEM>>>(
        h, w_fc1, b_fc1, nullptr, fc1, M_, HID_, C_);
    // 7) out = x1 + fc1 @ w_fc2 + b_fc2
    gemm_tc<EPI_BIAS_RES><<<dim3(C_ / 128, MB), 256, GEMM_SMEM>>>(
        fc1, w_fc2, b_fc2, x1, out, M_, C_, HID_);
}